// round 11
// baseline (speedup 1.0000x reference)
#include <cuda_runtime.h>

#define N_NODES 100000
#define NP      100032          // padded to 1563*64
#define N_EDGES 1600000
#define C_IN    128
#define C       64
#define HID3    256
#define SCAN_B  512
#define SCAN_NB 196   // ceil(100000/512)

// ---------------- scratch (device globals; no allocation allowed) ----------
__device__ int   g_is64;
__device__ int   g_deg[N_NODES];
__device__ float g_dinv[N_NODES];
__device__ int   g_rowptr[N_NODES + 1];
__device__ int   g_writepos[N_NODES];
__device__ int   g_blocksums[SCAN_B];
__device__ int   g_colsrc[N_EDGES];
__device__ float g_bufA[NP * C];       // GEMM outputs land here (padded)
__device__ float g_bufB[NP * C];       // aggregation outputs (padding stays 0)
__device__ float g_Wc[C * C];          // W3@W4 folded
__device__ float g_bc[C];              // b3@W4 + b4 folded

// ---------------- packed f32x2 helpers (Blackwell FFMA2) --------------------
__device__ __forceinline__ unsigned long long pk2(float lo, float hi) {
    unsigned long long r;
    asm("mov.b64 %0, {%1, %2};" : "=l"(r) : "f"(lo), "f"(hi));
    return r;
}
__device__ __forceinline__ void ffma2(unsigned long long& acc,
                                      unsigned long long a, unsigned long long b) {
    asm("fma.rn.f32x2 %0, %1, %2, %3;" : "=l"(acc) : "l"(a), "l"(b), "l"(acc));
}
__device__ __forceinline__ float2 upk2(unsigned long long v) {
    float2 f;
    asm("mov.b64 {%0, %1}, %2;" : "=f"(f.x), "=f"(f.y) : "l"(v));
    return f;
}

// ---------------- zero deg + dtype probe ------------------------------------
__global__ void k_zero_probe(const int* __restrict__ ei32) {
    int i = blockIdx.x * blockDim.x + threadIdx.x;
    if (i < N_NODES) g_deg[i] = 0;
    if (i == 0) {
        int all_hi_zero = 1;
        #pragma unroll 1
        for (int j = 0; j < 256; j++)
            if (ei32[2 * j + 1] != 0) { all_hi_zero = 0; break; }
        g_is64 = all_hi_zero;
    }
}

__global__ void k_build(const void* __restrict__ ei) {
    int e = blockIdx.x * blockDim.x + threadIdx.x;
    if (e >= N_EDGES) return;
    int d;
    if (g_is64) {
        const long long* p = (const long long*)ei;
        int s = (int)p[e];
        d = (int)p[N_EDGES + e];
        if ((unsigned)s >= N_NODES || (unsigned)d >= N_NODES) d = 0;
    } else {
        const int* p = (const int*)ei;
        int s = p[e];
        d = p[N_EDGES + e];
        if ((unsigned)s >= N_NODES || (unsigned)d >= N_NODES) d = 0;
    }
    atomicAdd(&g_deg[d], 1);
}

// exclusive scan of g_deg -> g_rowptr (3-phase block scan); also emits dinv
__global__ void k_scan1() {
    __shared__ int sh[SCAN_B];
    int t = threadIdx.x;
    int i = blockIdx.x * SCAN_B + t;
    int v = (i < N_NODES) ? g_deg[i] : 0;
    if (i < N_NODES) g_dinv[i] = rsqrtf((float)v + 1.0f);
    sh[t] = v;
    __syncthreads();
    for (int off = 1; off < SCAN_B; off <<= 1) {
        int add = (t >= off) ? sh[t - off] : 0;
        __syncthreads();
        sh[t] += add;
        __syncthreads();
    }
    if (i < N_NODES) g_rowptr[i] = sh[t] - v;   // exclusive
    if (t == SCAN_B - 1) g_blocksums[blockIdx.x] = sh[t];
}

// block 0: scan of block sums.  blocks 1..8: folded W3@W4 (+bc).
__global__ void k_scan2_wc(const float* __restrict__ W3, const float* __restrict__ W4,
                           const float* __restrict__ b3, const float* __restrict__ b4) {
    if (blockIdx.x == 0) {
        __shared__ int sh[SCAN_B];
        int t = threadIdx.x;
        int v = (t < SCAN_NB) ? g_blocksums[t] : 0;
        sh[t] = v;
        __syncthreads();
        for (int off = 1; off < SCAN_B; off <<= 1) {
            int add = (t >= off) ? sh[t - off] : 0;
            __syncthreads();
            sh[t] += add;
            __syncthreads();
        }
        if (t < SCAN_NB) g_blocksums[t] = sh[t] - v;
    } else {
        int gid = (blockIdx.x - 1) * SCAN_B + threadIdx.x;  // 0..4095
        int i = gid >> 6;    // 0..63
        int c = gid & 63;
        float acc = 0.0f;
        for (int j = 0; j < HID3; j++)
            acc = fmaf(W3[i * HID3 + j], W4[j * C + c], acc);
        g_Wc[i * C + c] = acc;
        if (i == 0) {
            float accb = 0.0f;
            for (int j = 0; j < HID3; j++)
                accb = fmaf(b3[j], W4[j * C + c], accb);
            g_bc[c] = accb + b4[c];
        }
    }
}

__global__ void k_scan3() {
    int i = blockIdx.x * SCAN_B + threadIdx.x;
    if (i < N_NODES) {
        int r = g_rowptr[i] + g_blocksums[blockIdx.x];
        g_rowptr[i]   = r;
        g_writepos[i] = r;
    }
    if (i == 0) g_rowptr[N_NODES] = N_EDGES;
}

__global__ void k_fill(const void* __restrict__ ei) {
    int e = blockIdx.x * blockDim.x + threadIdx.x;
    if (e >= N_EDGES) return;
    int s, d;
    if (g_is64) {
        const long long* p = (const long long*)ei;
        s = (int)p[e];
        d = (int)p[N_EDGES + e];
    } else {
        const int* p = (const int*)ei;
        s = p[e];
        d = p[N_EDGES + e];
    }
    if ((unsigned)s >= N_NODES || (unsigned)d >= N_NODES) { s = 0; d = 0; }
    int p2 = atomicAdd(&g_writepos[d], 1);
    g_colsrc[p2] = s;
}

// ---------------- GEMM: Y[NP][64] = X[NP][K] @ W[K][64] (+epilogue) --------
// 64 threads/block, tile M=64 rows, thread-tile 8 rows x 8 cols.
// LDS per kk per thread = 64B for 64 FMAs -> 1B/FMA (smem-cap balanced).
// MODE 0: X=ext(x, K=128),   W=ext,   Y = acc * dinv[row]   -> g_bufA
// MODE 1: X=g_bufB (K=64),   W=ext,   Y = acc * dinv[row]   -> g_bufA
// MODE 2: X=g_bufB (K=64),   W=g_Wc,  Y = acc + bc, fused log_softmax -> Out
template <int K, int MODE>
__global__ void k_gemm(const float* __restrict__ Xext, const float* __restrict__ Wext,
                       float* __restrict__ Out) {
    __shared__ float Xs[64][65];   // [row][kk], 65-pad: conflict-free column reads
    __shared__ float Ws[64][64];   // [kk][col]
    const float* X = (MODE == 0) ? Xext : g_bufB;
    const float* W = (MODE == 2) ? g_Wc : Wext;

    int tid  = threadIdx.x;        // 64 threads
    int rowg = tid >> 3;           // 8 row-groups x 8 rows
    int colg = tid & 7;            // 8 col-groups x 8 cols
    int row0 = blockIdx.x * 64;

    unsigned long long acc2[8][4] = {};  // [row][col-pair]

    for (int k0 = 0; k0 < K; k0 += 64) {
        #pragma unroll
        for (int idx = tid; idx < 64 * 16; idx += 64) {
            int r = idx >> 4, kq = idx & 15;
            int rr = row0 + r;
            if (MODE == 0) rr = min(rr, N_NODES - 1);   // external x not padded
            float4 v = *(const float4*)&X[rr * K + k0 + kq * 4];
            Xs[r][kq * 4 + 0] = v.x;
            Xs[r][kq * 4 + 1] = v.y;
            Xs[r][kq * 4 + 2] = v.z;
            Xs[r][kq * 4 + 3] = v.w;
        }
        #pragma unroll
        for (int idx = tid; idx < 64 * 16; idx += 64) {
            int kk = idx >> 4, cq = idx & 15;
            *(float4*)&Ws[kk][cq * 4] = *(const float4*)&W[(k0 + kk) * C + cq * 4];
        }
        __syncthreads();
        #pragma unroll 4
        for (int kk = 0; kk < 64; kk++) {
            ulonglong2 wa = *(const ulonglong2*)&Ws[kk][colg * 8];
            ulonglong2 wb = *(const ulonglong2*)&Ws[kk][colg * 8 + 4];
            #pragma unroll
            for (int j = 0; j < 8; j++) {
                float xv = Xs[rowg * 8 + j][kk];
                unsigned long long xp = pk2(xv, xv);
                ffma2(acc2[j][0], xp, wa.x);
                ffma2(acc2[j][1], xp, wa.y);
                ffma2(acc2[j][2], xp, wb.x);
                ffma2(acc2[j][3], xp, wb.y);
            }
        }
        __syncthreads();
    }

    if (MODE != 2) {
        #pragma unroll
        for (int j = 0; j < 8; j++) {
            int r = row0 + rowg * 8 + j;
            float s = (r < N_NODES) ? g_dinv[r] : 0.0f;
            float2 p0 = upk2(acc2[j][0]);
            float2 p1 = upk2(acc2[j][1]);
            float2 p2 = upk2(acc2[j][2]);
            float2 p3 = upk2(acc2[j][3]);
            float4 oa, ob;
            oa.x = p0.x * s; oa.y = p0.y * s; oa.z = p1.x * s; oa.w = p1.y * s;
            ob.x = p2.x * s; ob.y = p2.y * s; ob.z = p3.x * s; ob.w = p3.y * s;
            *(float4*)&g_bufA[r * C + colg * 8 + 0] = oa;
            *(float4*)&g_bufA[r * C + colg * 8 + 4] = ob;
        }
    } else {
        // stage logits (+bc) into Ws, then fused row log_softmax
        #pragma unroll
        for (int j = 0; j < 8; j++) {
            float2 p0 = upk2(acc2[j][0]);
            float2 p1 = upk2(acc2[j][1]);
            float2 p2 = upk2(acc2[j][2]);
            float2 p3 = upk2(acc2[j][3]);
            float4 oa, ob;
            oa.x = p0.x + g_bc[colg * 8 + 0];
            oa.y = p0.y + g_bc[colg * 8 + 1];
            oa.z = p1.x + g_bc[colg * 8 + 2];
            oa.w = p1.y + g_bc[colg * 8 + 3];
            ob.x = p2.x + g_bc[colg * 8 + 4];
            ob.y = p2.y + g_bc[colg * 8 + 5];
            ob.z = p3.x + g_bc[colg * 8 + 6];
            ob.w = p3.y + g_bc[colg * 8 + 7];
            *(float4*)&Ws[rowg * 8 + j][colg * 8 + 0] = oa;
            *(float4*)&Ws[rowg * 8 + j][colg * 8 + 4] = ob;
        }
        __syncthreads();
        int wid  = tid >> 5;    // 2 warps, 32 rows each
        int lane = tid & 31;
        #pragma unroll 4
        for (int j = 0; j < 32; j++) {
            int r = wid * 32 + j;
            float y0 = Ws[r][lane];
            float y1 = Ws[r][lane + 32];
            float m = fmaxf(y0, y1);
            #pragma unroll
            for (int off = 16; off; off >>= 1)
                m = fmaxf(m, __shfl_xor_sync(0xffffffffu, m, off));
            float se = expf(y0 - m) + expf(y1 - m);
            #pragma unroll
            for (int off = 16; off; off >>= 1)
                se += __shfl_xor_sync(0xffffffffu, se, off);
            float lse = m + logf(se);
            int rg2 = row0 + r;
            if (rg2 < N_NODES) {
                Out[rg2 * C + lane]      = y0 - lse;
                Out[rg2 * C + lane + 32] = y1 - lse;
            }
        }
    }
}

// ---------------- CSR aggregation: bufB = relu(dinv*(sum+self) + b) --------
__global__ void k_agg(const float* __restrict__ bias) {
    int warp = (blockIdx.x * blockDim.x + threadIdx.x) >> 5;
    int lane = threadIdx.x & 31;
    if (warp >= N_NODES) return;

    const float2* H2 = (const float2*)g_bufA;
    float2 acc = H2[warp * 32 + lane];          // self-loop term (h_s[i])
    int beg = g_rowptr[warp];
    int end = g_rowptr[warp + 1];
    int e = beg;
    for (; e + 4 <= end; e += 4) {
        int s0 = g_colsrc[e + 0];
        int s1 = g_colsrc[e + 1];
        int s2 = g_colsrc[e + 2];
        int s3 = g_colsrc[e + 3];
        float2 v0 = H2[s0 * 32 + lane];
        float2 v1 = H2[s1 * 32 + lane];
        float2 v2 = H2[s2 * 32 + lane];
        float2 v3 = H2[s3 * 32 + lane];
        acc.x += (v0.x + v1.x) + (v2.x + v3.x);
        acc.y += (v0.y + v1.y) + (v2.y + v3.y);
    }
    for (; e < end; e++) {
        int s = g_colsrc[e];
        float2 v = H2[s * 32 + lane];
        acc.x += v.x;
        acc.y += v.y;
    }
    float d = g_dinv[warp];
    float2 b = ((const float2*)bias)[lane];
    float2 o;
    o.x = fmaxf(fmaf(acc.x, d, b.x), 0.0f);
    o.y = fmaxf(fmaf(acc.y, d, b.y), 0.0f);
    ((float2*)g_bufB)[warp * 32 + lane] = o;
}

// ---------------- launch ----------------------------------------------------
extern "C" void kernel_launch(void* const* d_in, const int* in_sizes, int n_in,
                              void* d_out, int out_size) {
    const float* x  = (const float*)d_in[0];
    const void*  ei = d_in[1];
    const float* W1 = (const float*)d_in[2];
    const float* b1 = (const float*)d_in[3];
    const float* W2 = (const float*)d_in[4];
    const float* b2 = (const float*)d_in[5];
    const float* W3 = (const float*)d_in[6];
    const float* b3 = (const float*)d_in[7];
    const float* W4 = (const float*)d_in[8];
    const float* b4 = (const float*)d_in[9];
    float* out = (float*)d_out;

    const int NODE_BLK = (N_NODES + 255) / 256;
    const int EDGE_BLK = (N_EDGES + 255) / 256;
    const int WARP_BLK = (N_NODES * 32 + 255) / 256;
    const int GEMM_BLK = NP / 64;   // 1563

    // CSR + degree preprocessing
    k_zero_probe<<<NODE_BLK, 256>>>((const int*)ei);
    k_build<<<EDGE_BLK, 256>>>(ei);
    k_scan1<<<SCAN_NB, SCAN_B>>>();
    k_scan2_wc<<<9, SCAN_B>>>(W3, W4, b3, b4);
    k_scan3<<<SCAN_NB, SCAN_B>>>();
    k_fill<<<EDGE_BLK, 256>>>(ei);

    // Layer 1: h_s = (x@W1)*dinv ; agg+relu
    k_gemm<C_IN, 0><<<GEMM_BLK, 64>>>(x, W1, nullptr);
    k_agg<<<WARP_BLK, 256>>>(b1);

    // Layer 2: h_s = (relu1@W2)*dinv ; agg+relu
    k_gemm<C, 1><<<GEMM_BLK, 64>>>(x, W2, nullptr);
    k_agg<<<WARP_BLK, 256>>>(b2);

    // Folded linear + log_softmax (fused)
    k_gemm<C, 2><<<GEMM_BLK, 64>>>(x, W2, out);
}

// round 14
// speedup vs baseline: 1.3416x; 1.3416x over previous
#include <cuda_runtime.h>
#include <cuda_fp16.h>

#define N_NODES 100000
#define N_EDGES 1600000
#define C_IN    128
#define C       64
#define HID3    256
#define SCAN_B  512
#define SCAN_NB 196   // ceil(100000/512)

// ---------------- scratch (device globals; no allocation allowed) ----------
__device__ int     g_is64;
__device__ int     g_deg[N_NODES];
__device__ float   g_dinv[N_NODES];
__device__ int     g_rowptr[N_NODES + 1];
__device__ int     g_writepos[N_NODES];
__device__ int     g_blocksums[SCAN_B];
__device__ int     g_colsrc[N_EDGES];
__device__ __half2 g_bufA[N_NODES * 32];   // h*dinv, fp16 (gather payload)
__device__ float   g_bufB[N_NODES * C];    // aggregation outputs (fp32)
__device__ float   g_Wc[C * C];            // W3@W4 folded
__device__ float   g_bc[C];                // b3@W4 + b4 folded

// ---------------- packed f32x2 helpers (Blackwell FFMA2) --------------------
__device__ __forceinline__ unsigned long long pk2(float lo, float hi) {
    unsigned long long r;
    asm("mov.b64 %0, {%1, %2};" : "=l"(r) : "f"(lo), "f"(hi));
    return r;
}
__device__ __forceinline__ void ffma2(unsigned long long& acc,
                                      unsigned long long a, unsigned long long b) {
    asm("fma.rn.f32x2 %0, %1, %2, %3;" : "=l"(acc) : "l"(a), "l"(b), "l"(acc));
}
__device__ __forceinline__ float2 upk2(unsigned long long v) {
    float2 f;
    asm("mov.b64 {%0, %1}, %2;" : "=f"(f.x), "=f"(f.y) : "l"(v));
    return f;
}

// ---------------- zero deg + dtype probe ------------------------------------
__global__ void k_zero_probe(const int* __restrict__ ei32) {
    int i = blockIdx.x * blockDim.x + threadIdx.x;
    if (i < N_NODES) g_deg[i] = 0;
    if (i == 0) {
        int all_hi_zero = 1;
        #pragma unroll 1
        for (int j = 0; j < 256; j++)
            if (ei32[2 * j + 1] != 0) { all_hi_zero = 0; break; }
        g_is64 = all_hi_zero;
    }
}

__global__ void k_build(const void* __restrict__ ei) {
    int e = blockIdx.x * blockDim.x + threadIdx.x;
    if (e >= N_EDGES) return;
    int d;
    if (g_is64) {
        const long long* p = (const long long*)ei;
        int s = (int)p[e];
        d = (int)p[N_EDGES + e];
        if ((unsigned)s >= N_NODES || (unsigned)d >= N_NODES) d = 0;
    } else {
        const int* p = (const int*)ei;
        int s = p[e];
        d = p[N_EDGES + e];
        if ((unsigned)s >= N_NODES || (unsigned)d >= N_NODES) d = 0;
    }
    atomicAdd(&g_deg[d], 1);
}

// exclusive scan of g_deg -> g_rowptr (3-phase block scan); also emits dinv
__global__ void k_scan1() {
    __shared__ int sh[SCAN_B];
    int t = threadIdx.x;
    int i = blockIdx.x * SCAN_B + t;
    int v = (i < N_NODES) ? g_deg[i] : 0;
    if (i < N_NODES) g_dinv[i] = rsqrtf((float)v + 1.0f);
    sh[t] = v;
    __syncthreads();
    for (int off = 1; off < SCAN_B; off <<= 1) {
        int add = (t >= off) ? sh[t - off] : 0;
        __syncthreads();
        sh[t] += add;
        __syncthreads();
    }
    if (i < N_NODES) g_rowptr[i] = sh[t] - v;   // exclusive
    if (t == SCAN_B - 1) g_blocksums[blockIdx.x] = sh[t];
}

__global__ void k_scan2() {
    __shared__ int sh[SCAN_B];
    int t = threadIdx.x;
    int v = (t < SCAN_NB) ? g_blocksums[t] : 0;
    sh[t] = v;
    __syncthreads();
    for (int off = 1; off < SCAN_B; off <<= 1) {
        int add = (t >= off) ? sh[t - off] : 0;
        __syncthreads();
        sh[t] += add;
        __syncthreads();
    }
    if (t < SCAN_NB) g_blocksums[t] = sh[t] - v;  // exclusive over block sums
}

__global__ void k_scan3() {
    int i = blockIdx.x * SCAN_B + threadIdx.x;
    if (i < N_NODES) {
        int r = g_rowptr[i] + g_blocksums[blockIdx.x];
        g_rowptr[i]   = r;
        g_writepos[i] = r;
    }
    if (i == 0) g_rowptr[N_NODES] = N_EDGES;
}

__global__ void k_fill(const void* __restrict__ ei) {
    int e = blockIdx.x * blockDim.x + threadIdx.x;
    if (e >= N_EDGES) return;
    int s, d;
    if (g_is64) {
        const long long* p = (const long long*)ei;
        s = (int)p[e];
        d = (int)p[N_EDGES + e];
    } else {
        const int* p = (const int*)ei;
        s = p[e];
        d = p[N_EDGES + e];
    }
    if ((unsigned)s >= N_NODES || (unsigned)d >= N_NODES) { s = 0; d = 0; }
    int p2 = atomicAdd(&g_writepos[d], 1);
    g_colsrc[p2] = s;
}

// ---------------- folded linear weights, parallel over K --------------------
// grid 65, block 256: blocks 0..63 -> row i of Wc; block 64 -> bc.
// K=256 split 4 ways per thread (64 coalesced W4 loads each), smem reduce.
__global__ void k_wc(const float* __restrict__ W3, const float* __restrict__ W4,
                     const float* __restrict__ b3, const float* __restrict__ b4) {
    __shared__ float w3row[HID3];
    __shared__ float part[4][C];
    int c  = threadIdx.x & 63;
    int jq = threadIdx.x >> 6;           // 0..3
    if (blockIdx.x < 64) {
        int i = blockIdx.x;
        w3row[threadIdx.x] = W3[i * HID3 + threadIdx.x];
        __syncthreads();
        float acc = 0.0f;
        #pragma unroll 8
        for (int jj = 0; jj < 64; jj++) {
            int j = jq * 64 + jj;
            acc = fmaf(w3row[j], W4[j * C + c], acc);
        }
        part[jq][c] = acc;
        __syncthreads();
        if (jq == 0)
            g_Wc[i * C + c] = (part[0][c] + part[1][c]) + (part[2][c] + part[3][c]);
    } else {
        float acc = 0.0f;
        #pragma unroll 8
        for (int jj = 0; jj < 64; jj++) {
            int j = jq * 64 + jj;
            acc = fmaf(b3[j], W4[j * C + c], acc);
        }
        part[jq][c] = acc;
        __syncthreads();
        if (jq == 0)
            g_bc[c] = (part[0][c] + part[1][c]) + (part[2][c] + part[3][c]) + b4[c];
    }
}

// ---------------- GEMM: Y[N][64] = X[N][K] @ W[K][64] (+epilogue) ----------
// MODE 0: X=ext(x, K=128),   W=ext,   bufA = fp16(acc * dinv[row])
// MODE 1: X=g_bufB (K=64),   W=ext,   bufA = fp16(acc * dinv[row])
// MODE 2: X=g_bufB (K=64),   W=g_Wc,  acc + bc, fused log_softmax -> Out
// 128 threads: 8 row-groups x 4 rows, 16 col-groups x 4 cols (2 packed pairs).
template <int K, int MODE>
__global__ void k_gemm(const float* __restrict__ Xext, const float* __restrict__ Wext,
                       float* __restrict__ Out) {
    __shared__ float Xs[32][64];
    __shared__ float Ws[64][64];
    const float* X = (MODE == 0) ? Xext : g_bufB;
    const float* W = (MODE == 2) ? g_Wc : Wext;

    int tid = threadIdx.x;          // 128 threads
    int cg  = tid & 15;             // 16 col-groups x 4 cols
    int rg  = tid >> 4;             // 8 row-groups x 4 rows
    int row0 = blockIdx.x * 32;

    unsigned long long acc2[4][2] = {};  // [row][col-pair], packed f32x2

    for (int k0 = 0; k0 < K; k0 += 64) {
        #pragma unroll
        for (int idx = tid; idx < 32 * 16; idx += 128) {
            int r = idx >> 4, kq = idx & 15;
            *(float4*)&Xs[r][kq * 4] = *(const float4*)&X[(row0 + r) * K + k0 + kq * 4];
        }
        #pragma unroll
        for (int idx = tid; idx < 64 * 16; idx += 128) {
            int kk = idx >> 4, cq = idx & 15;
            *(float4*)&Ws[kk][cq * 4] = *(const float4*)&W[(k0 + kk) * C + cq * 4];
        }
        __syncthreads();
        #pragma unroll 16
        for (int kk = 0; kk < 64; kk++) {
            ulonglong2 wp = *(const ulonglong2*)&Ws[kk][cg * 4];
            unsigned long long x0 = pk2(Xs[rg * 4 + 0][kk], Xs[rg * 4 + 0][kk]);
            unsigned long long x1 = pk2(Xs[rg * 4 + 1][kk], Xs[rg * 4 + 1][kk]);
            unsigned long long x2 = pk2(Xs[rg * 4 + 2][kk], Xs[rg * 4 + 2][kk]);
            unsigned long long x3 = pk2(Xs[rg * 4 + 3][kk], Xs[rg * 4 + 3][kk]);
            ffma2(acc2[0][0], x0, wp.x); ffma2(acc2[0][1], x0, wp.y);
            ffma2(acc2[1][0], x1, wp.x); ffma2(acc2[1][1], x1, wp.y);
            ffma2(acc2[2][0], x2, wp.x); ffma2(acc2[2][1], x2, wp.y);
            ffma2(acc2[3][0], x3, wp.x); ffma2(acc2[3][1], x3, wp.y);
        }
        __syncthreads();
    }

    if (MODE != 2) {
        #pragma unroll
        for (int j = 0; j < 4; j++) {
            int r = row0 + rg * 4 + j;
            float s = g_dinv[r];
            float2 p0 = upk2(acc2[j][0]);
            float2 p1 = upk2(acc2[j][1]);
            __half2 h0 = __floats2half2_rn(p0.x * s, p0.y * s);
            __half2 h1 = __floats2half2_rn(p1.x * s, p1.y * s);
            uint2 u;
            u.x = *(const unsigned int*)&h0;
            u.y = *(const unsigned int*)&h1;
            *(uint2*)&g_bufA[r * 32 + cg * 2] = u;   // 8B store, cols cg*4..cg*4+3
        }
    } else {
        // epilogue: +bc, stage tile into Xs (reused), then fused log_softmax
        #pragma unroll
        for (int j = 0; j < 4; j++) {
            float2 p0 = upk2(acc2[j][0]);
            float2 p1 = upk2(acc2[j][1]);
            float4 o;
            o.x = p0.x + g_bc[cg * 4 + 0];
            o.y = p0.y + g_bc[cg * 4 + 1];
            o.z = p1.x + g_bc[cg * 4 + 2];
            o.w = p1.y + g_bc[cg * 4 + 3];
            *(float4*)&Xs[rg * 4 + j][cg * 4] = o;
        }
        __syncthreads();
        int wid  = tid >> 5;   // 4 warps, 8 rows each
        int lane = tid & 31;
        #pragma unroll
        for (int j = 0; j < 8; j++) {
            int r = wid * 8 + j;
            float2 y = ((const float2*)&Xs[r][0])[lane];
            float m = fmaxf(y.x, y.y);
            #pragma unroll
            for (int off = 16; off; off >>= 1)
                m = fmaxf(m, __shfl_xor_sync(0xffffffffu, m, off));
            float se = expf(y.x - m) + expf(y.y - m);
            #pragma unroll
            for (int off = 16; off; off >>= 1)
                se += __shfl_xor_sync(0xffffffffu, se, off);
            float lse = m + logf(se);
            float2 o;
            o.x = y.x - lse;
            o.y = y.y - lse;
            ((float2*)&Out[(row0 + r) * C])[lane] = o;
        }
    }
}

// ---------------- CSR aggregation: bufB = relu(dinv*(sum+self) + b) --------
// g_bufA holds h_s = h*dinv in fp16 (half2 per lane = 4B; 128B per warp-edge).
// One warp per node; accumulate in fp32.
__global__ void k_agg(const float* __restrict__ bias) {
    int warp = (blockIdx.x * blockDim.x + threadIdx.x) >> 5;
    int lane = threadIdx.x & 31;
    if (warp >= N_NODES) return;

    const __half2* H = g_bufA;
    float2 acc = __half22float2(H[warp * 32 + lane]);   // self-loop term
    int beg = g_rowptr[warp];
    int end = g_rowptr[warp + 1];
    int e = beg;
    for (; e + 4 <= end; e += 4) {
        int s0 = g_colsrc[e + 0];
        int s1 = g_colsrc[e + 1];
        int s2 = g_colsrc[e + 2];
        int s3 = g_colsrc[e + 3];
        float2 v0 = __half22float2(H[s0 * 32 + lane]);
        float2 v1 = __half22float2(H[s1 * 32 + lane]);
        float2 v2 = __half22float2(H[s2 * 32 + lane]);
        float2 v3 = __half22float2(H[s3 * 32 + lane]);
        acc.x += (v0.x + v1.x) + (v2.x + v3.x);
        acc.y += (v0.y + v1.y) + (v2.y + v3.y);
    }
    for (; e < end; e++) {
        int s = g_colsrc[e];
        float2 v = __half22float2(H[s * 32 + lane]);
        acc.x += v.x;
        acc.y += v.y;
    }
    float d = g_dinv[warp];
    float2 b = ((const float2*)bias)[lane];
    float2 o;
    o.x = fmaxf(fmaf(acc.x, d, b.x), 0.0f);
    o.y = fmaxf(fmaf(acc.y, d, b.y), 0.0f);
    ((float2*)g_bufB)[warp * 32 + lane] = o;
}

// ---------------- launch ----------------------------------------------------
extern "C" void kernel_launch(void* const* d_in, const int* in_sizes, int n_in,
                              void* d_out, int out_size) {
    const float* x  = (const float*)d_in[0];
    const void*  ei = d_in[1];
    const float* W1 = (const float*)d_in[2];
    const float* b1 = (const float*)d_in[3];
    const float* W2 = (const float*)d_in[4];
    const float* b2 = (const float*)d_in[5];
    const float* W3 = (const float*)d_in[6];
    const float* b3 = (const float*)d_in[7];
    const float* W4 = (const float*)d_in[8];
    const float* b4 = (const float*)d_in[9];
    float* out = (float*)d_out;

    const int NODE_BLK = (N_NODES + 255) / 256;
    const int EDGE_BLK = (N_EDGES + 255) / 256;
    const int WARP_BLK = (N_NODES * 32 + 255) / 256;
    const int GEMM_BLK = N_NODES / 32;   // 3125, exact

    // CSR + degree preprocessing
    k_zero_probe<<<NODE_BLK, 256>>>((const int*)ei);
    k_build<<<EDGE_BLK, 256>>>(ei);
    k_scan1<<<SCAN_NB, SCAN_B>>>();
    k_scan2<<<1, SCAN_B>>>();
    k_scan3<<<SCAN_NB, SCAN_B>>>();
    k_fill<<<EDGE_BLK, 256>>>(ei);

    // Folded W3@W4 (parallel over K)
    k_wc<<<65, 256>>>(W3, W4, b3, b4);

    // Layer 1: h_s = (x@W1)*dinv ; agg+relu
    k_gemm<C_IN, 0><<<GEMM_BLK, 128>>>(x, W1, nullptr);
    k_agg<<<WARP_BLK, 256>>>(b1);

    // Layer 2: h_s = (relu1@W2)*dinv ; agg+relu
    k_gemm<C, 1><<<GEMM_BLK, 128>>>(x, W2, nullptr);
    k_agg<<<WARP_BLK, 256>>>(b2);

    // Folded linear + log_softmax (fused)
    k_gemm<C, 2><<<GEMM_BLK, 128>>>(x, W2, out);
}